// round 7
// baseline (speedup 1.0000x reference)
#include <cuda_runtime.h>

#define IMG   256
#define F_CNT 256

// linspace(-1,1,256)[k]: XLA lowers start + iota*step, LLVM contracts to
// fma(k, step, -1). Endpoint exact.
__device__ __forceinline__ float lin_at(int k) {
    const float STEP = 2.0f / 255.0f;
    if (k == 255) return 1.0f;
    return __fmaf_rn((float)k, STEP, -1.0f);
}

// edge value at (qx,qy), anchored (ex,ey), deltas (dy,dx):
// E = fma(qx-ex, dy, -((qy-ey)*dx))   (bit-identical to reference contraction)
__device__ __forceinline__ float edge_at(float qx, float qy, float ex, float ey,
                                         float dy, float dx) {
    return __fmaf_rn(__fsub_rn(qx, ex), dy, -__fmul_rn(__fsub_rn(qy, ey), dx));
}

__global__ void __launch_bounds__(1024, 2) render_kernel(
    const float* __restrict__ vertices,
    const void*  __restrict__ faces,
    const float* __restrict__ uv,
    const void*  __restrict__ uvfaces,
    const float* __restrict__ uvmap,
    float*       __restrict__ out)
{
    // per-face packed (compacted, tile-local):
    // [0]=(bx,by,ay-by,ax-bx) [1]=(cx,cy,by-cy,bx-cx) [2]=(ax,ay,cy-ay,cx-ax)
    // [3]=(Asafe,zi0,zi1,zi2) [4]=(u0,v0,u1,v1) [5]=(u2,v2,-,-)
    __shared__ float4 sf[F_CNT][6];
    __shared__ unsigned long long skey[4][256];
    __shared__ float s_warpmin[32];
    __shared__ float s_tthr;
    __shared__ int s_isf64, s_isu64;
    __shared__ int warpcnt[8];

    const int tx = threadIdx.x, ty = threadIdx.y, tz = threadIdx.z;
    const int tid  = tx + ty * 16 + tz * 256;
    const int wid  = tid >> 5, lane = tid & 31;
    const int jt0 = blockIdx.x * 16, it0 = blockIdx.y * 16;

    // ---- speculative int32 index preload (in-bounds for either dtype) ----
    int p0 = 0, p1 = 0, p2 = 0, q0 = 0, q1 = 0, q2 = 0;
    if (tid < 256) {
        const int* pf = (const int*)faces;
        const int* pu = (const int*)uvfaces;
        p0 = pf[tid*3]; p1 = pf[tid*3+1]; p2 = pf[tid*3+2];
        q0 = pu[tid*3]; q1 = pu[tid*3+1]; q2 = pu[tid*3+2];
    }

    // ---- dtype probe: odd 32-bit words of first 32 int64 entries are 0.
    // (reading words 1..63 is in-bounds for int32 too; P(32 random idx==0)~0)
    if (wid == 0) {
        unsigned w = ((const unsigned*)faces)[2*lane + 1];
        bool any = __any_sync(0xffffffffu, w != 0u);
        if (lane == 0) s_isf64 = !any;
    } else if (wid == 1) {
        unsigned w = ((const unsigned*)uvfaces)[2*lane + 1];
        bool any = __any_sync(0xffffffffu, w != 0u);
        if (lane == 0) s_isu64 = !any;
    }

    // ---- min-z partial reduce (1024 threads, 1 vertex each) ----
    float zm = vertices[tid * 3 + 2];
    #pragma unroll
    for (int o = 16; o; o >>= 1) zm = fminf(zm, __shfl_xor_sync(0xffffffffu, zm, o));
    if (lane == 0) s_warpmin[wid] = zm;
    __syncthreads();   // #1

    // ---- phase 1: per-face precompute + tile cull (warps 0..7) ----
    float4 fd[6];
    bool flag = false;
    if (tid < 256) {
        long long i0, i1, i2, j0, j1, j2;
        if (!s_isf64) { i0 = p0; i1 = p1; i2 = p2; }
        else {
            const long long* p = (const long long*)faces;
            i0 = p[tid*3]; i1 = p[tid*3+1]; i2 = p[tid*3+2];
        }
        if (!s_isu64) { j0 = q0; j1 = q1; j2 = q2; }
        else {
            const long long* p = (const long long*)uvfaces;
            j0 = p[tid*3]; j1 = p[tid*3+1]; j2 = p[tid*3+2];
        }

        float ax = vertices[i0*3+0], ay = vertices[i0*3+1], az = vertices[i0*3+2];
        float bx = vertices[i1*3+0], by = vertices[i1*3+1], bz = vertices[i1*3+2];
        float cx = vertices[i2*3+0], cy = vertices[i2*3+1], cz = vertices[i2*3+2];

        // signed 2D area, LLVM-contracted: fma(d1, d2, -(d3*d4))
        float A = __fmaf_rn(__fsub_rn(bx, ax), __fsub_rn(cy, ay),
                            -__fmul_rn(__fsub_rn(by, ay), __fsub_rn(cx, ax)));
        float Asafe = (fabsf(A) < 1e-9f) ? 1.0f : A;

        float zi0 = __fdiv_rn(1.0f, az);
        float zi1 = __fdiv_rn(1.0f, bz);
        float zi2 = __fdiv_rn(1.0f, cz);

        // uvn = uv*2 - 1 contracts to fma(uv,2,-1); then * z_inv
        float u0 = __fmul_rn(__fmaf_rn(uv[j0*2+0], 2.0f, -1.0f), zi0);
        float v0 = __fmul_rn(__fmaf_rn(uv[j0*2+1], 2.0f, -1.0f), zi0);
        float u1 = __fmul_rn(__fmaf_rn(uv[j1*2+0], 2.0f, -1.0f), zi1);
        float v1 = __fmul_rn(__fmaf_rn(uv[j1*2+1], 2.0f, -1.0f), zi1);
        float u2 = __fmul_rn(__fmaf_rn(uv[j2*2+0], 2.0f, -1.0f), zi2);
        float v2 = __fmul_rn(__fmaf_rn(uv[j2*2+1], 2.0f, -1.0f), zi2);

        fd[0] = make_float4(bx, by, __fsub_rn(ay, by), __fsub_rn(ax, bx));
        fd[1] = make_float4(cx, cy, __fsub_rn(by, cy), __fsub_rn(bx, cx));
        fd[2] = make_float4(ax, ay, __fsub_rn(cy, ay), __fsub_rn(cx, ax));
        fd[3] = make_float4(Asafe, zi0, zi1, zi2);
        fd[4] = make_float4(u0, v0, u1, v1);
        fd[5] = make_float4(u2, v2, 0.f, 0.f);

        if (A >= 1e-9f) {
            // bbox pre-filter (±1 px margin)
            float minx = fminf(ax, fminf(bx, cx)), maxx = fmaxf(ax, fmaxf(bx, cx));
            float miny = fminf(ay, fminf(by, cy)), maxy = fmaxf(ay, fmaxf(by, cy));
            int jlo = max(0,   (int)floorf((minx + 1.0f) * 127.5f) - 1);
            int jhi = min(255, (int)ceilf ((maxx + 1.0f) * 127.5f) + 1);
            int klo = max(0,   (int)floorf((miny + 1.0f) * 127.5f) - 1);
            int khi = min(255, (int)ceilf ((maxy + 1.0f) * 127.5f) + 1);
            int ilo = 255 - khi, ihi = 255 - klo;
            flag = (jlo <= jt0 + 15) && (jhi >= jt0) && (ilo <= it0 + 15) && (ihi >= it0);

            if (flag) {
                // conservative tile-corner edge cull
                const float MARGIN = -1e-3f;
                float qx0 = lin_at(jt0), qx1 = lin_at(jt0 + 15);
                float qy0 = lin_at(255 - (it0 + 15)), qy1 = lin_at(255 - it0);
                #pragma unroll
                for (int e = 0; e < 3; e++) {
                    float ex = fd[e].x, ey = fd[e].y, dy = fd[e].z, dx = fd[e].w;
                    float m = fmaxf(fmaxf(edge_at(qx0, qy0, ex, ey, dy, dx),
                                          edge_at(qx1, qy0, ex, ey, dy, dx)),
                                    fmaxf(edge_at(qx0, qy1, ex, ey, dy, dx),
                                          edge_at(qx1, qy1, ex, ey, dy, dx)));
                    if (m < MARGIN) flag = false;
                }
            }
        }
    }

    unsigned bmask = 0;
    if (wid < 8) {
        bmask = __ballot_sync(0xffffffffu, flag);
        if (lane == 0) warpcnt[wid] = __popc(bmask);
    } else if (wid == 31) {
        // ---- zmin finish + parallel ulp search for t* (overlapped with phase 1)
        float z = s_warpmin[lane];
        #pragma unroll
        for (int o = 16; o; o >>= 1) z = fminf(z, __shfl_xor_sync(0xffffffffu, z, o));
        z = __shfl_sync(0xffffffffu, z, 0);
        // t* = max{ t : fdiv(1,t) >= zinit }  =>  (Z>=zinit) <=> (zinv<=t*)
        float t0 = __fdiv_rn(1.0f, z);
        int im = -1;
        if (lane < 9) {
            unsigned cb = __float_as_uint(t0) + (unsigned)(lane - 4);
            float c = __uint_as_float(cb);
            if (__fdiv_rn(1.0f, c) >= z) im = (int)cb;
        }
        im = __reduce_max_sync(0xffffffffu, im);
        if (lane == 0) s_tthr = __uint_as_float((unsigned)im);
    }
    __syncthreads();   // #2

    // ---- offsets + stable compaction (no serial pass) ----
    int nf = 0, off = 0;
    #pragma unroll
    for (int w = 0; w < 8; w++) {
        int c = warpcnt[w];
        if (w < wid) off += c;
        nf += c;
    }
    if (flag) {
        int pos = off + __popc(bmask & ((1u << lane) - 1u));
        #pragma unroll
        for (int qq = 0; qq < 6; qq++) sf[pos][qq] = fd[qq];
    }
    __syncthreads();   // #3

    // ---- main loop: thread tz scans faces k = tz, tz+4, ... ----
    const float tthr = s_tthr;
    const int j = jt0 + tx, i = it0 + ty;
    const float px = lin_at(j);
    const float py = lin_at(255 - i);   // rot90: py = lin[255-i]

    // winner = lexicographic min of (zinv_bits, face_idx)  (argmax Z, first-tie)
    unsigned long long bestkey = ~0ull;
    for (int k = tz; k < nf; k += 4) {
        float4 e0 = sf[k][0];
        float4 e1 = sf[k][1];
        float4 e2 = sf[k][2];
        float pAB = edge_at(px, py, e0.x, e0.y, e0.z, e0.w);
        float pCB = edge_at(px, py, e1.x, e1.y, e1.z, e1.w);
        float pCA = edge_at(px, py, e2.x, e2.y, e2.z, e2.w);

        if (pAB > 0.0f && pCB > 0.0f && pCA > 0.0f) {
            float4 zz = sf[k][3];
            float w1 = __fdiv_rn(pCB, zz.x);
            float w2 = __fdiv_rn(pCA, zz.x);
            float w3 = __fsub_rn(__fsub_rn(1.0f, w1), w2);
            float zinv = __fmaf_rn(w3, zz.w,
                         __fmaf_rn(w1, zz.y,
                         __fmul_rn(w2, zz.z)));
            if (zinv <= tthr) {
                unsigned long long key =
                    ((unsigned long long)__float_as_uint(zinv) << 32) | (unsigned)k;
                if (key < bestkey) bestkey = key;
            }
        }
    }
    skey[tz][ty * 16 + tx] = bestkey;
    __syncthreads();   // #4

    // ---- epilogue: all 4 tz slices participate; tz=c shades channel c ----
    {
        int pix = ty * 16 + tx;
        unsigned long long key = skey[0][pix];
        unsigned long long k1 = skey[1][pix]; if (k1 < key) key = k1;
        unsigned long long k2 = skey[2][pix]; if (k2 < key) key = k2;
        unsigned long long k3 = skey[3][pix]; if (k3 < key) key = k3;

        int pidx = i * 256 + j;
        if (tz == 3) {
            out[3 * 65536 + pidx] = (key != ~0ull) ? 1.0f : 0.0f;
        } else {
            float val = 0.f;
            if (key != ~0ull) {
                int bk = (int)(key & 0xFFFFFFFFull);
                float zinv = __uint_as_float((unsigned)(key >> 32));
                float Zw = __fdiv_rn(1.0f, zinv);   // == reference Zw bitwise

                float4 e1v = sf[bk][1];
                float4 e2v = sf[bk][2];
                float4 zz  = sf[bk][3];
                float pCB = edge_at(px, py, e1v.x, e1v.y, e1v.z, e1v.w);
                float pCA = edge_at(px, py, e2v.x, e2v.y, e2v.z, e2v.w);
                float w1 = __fdiv_rn(pCB, zz.x);
                float w2 = __fdiv_rn(pCA, zz.x);
                float w3 = __fsub_rn(__fsub_rn(1.0f, w1), w2);

                float4 uva = sf[bk][4];
                float4 uvb = sf[bk][5];
                float u = __fmaf_rn(w3, uvb.x,
                          __fmaf_rn(w1, uva.x,
                          __fmul_rn(w2, uva.z)));
                float v = __fmaf_rn(w3, uvb.y,
                          __fmaf_rn(w1, uva.y,
                          __fmul_rn(w2, uva.w)));
                float gx = __fmul_rn(u, Zw);
                float gy = __fmul_rn(v, Zw);

                // x = ((gx+1)*256 - 1)*0.5, contracted to fma(gx+1, 256, -1)
                float x = __fmul_rn(__fmaf_rn(__fadd_rn(gx, 1.0f), 256.0f, -1.0f), 0.5f);
                float y = __fmul_rn(__fmaf_rn(__fadd_rn(gy, 1.0f), 256.0f, -1.0f), 0.5f);
                float x0 = floorf(x), y0 = floorf(y);
                float x1 = __fadd_rn(x0, 1.0f), y1 = __fadd_rn(y0, 1.0f);
                float wx1 = __fsub_rn(x, x0), wx0 = __fsub_rn(1.0f, wx1);
                float wy1 = __fsub_rn(y, y0), wy0 = __fsub_rn(1.0f, wy1);

                bool v00 = (x0 >= 0.f) && (x0 <= 255.f) && (y0 >= 0.f) && (y0 <= 255.f);
                bool v10 = (x1 >= 0.f) && (x1 <= 255.f) && (y0 >= 0.f) && (y0 <= 255.f);
                bool v01 = (x0 >= 0.f) && (x0 <= 255.f) && (y1 >= 0.f) && (y1 <= 255.f);
                bool v11 = (x1 >= 0.f) && (x1 <= 255.f) && (y1 >= 0.f) && (y1 <= 255.f);

                int ix0 = (int)fminf(fmaxf(x0, 0.f), 255.f);
                int ix1 = (int)fminf(fmaxf(x1, 0.f), 255.f);
                int iy0 = (int)fminf(fmaxf(y0, 0.f), 255.f);
                int iy1 = (int)fminf(fmaxf(y1, 0.f), 255.f);

                float w00 = __fmul_rn(wx0, wy0);
                float w10 = __fmul_rn(wx1, wy0);
                float w01 = __fmul_rn(wx0, wy1);
                float w11 = __fmul_rn(wx1, wy1);

                const float* img = uvmap + tz * 65536;
                float t00 = v00 ? __ldg(img + iy0 * 256 + ix0) : 0.f;
                float t10 = v10 ? __ldg(img + iy0 * 256 + ix1) : 0.f;
                float t01 = v01 ? __ldg(img + iy1 * 256 + ix0) : 0.f;
                float t11 = v11 ? __ldg(img + iy1 * 256 + ix1) : 0.f;
                val = __fmaf_rn(t11, w11,
                      __fmaf_rn(t01, w01,
                      __fmaf_rn(t00, w00,
                      __fmul_rn(t10, w10))));
            }
            out[tz * 65536 + pidx] = val;
        }
    }
}

extern "C" void kernel_launch(void* const* d_in, const int* in_sizes, int n_in,
                              void* d_out, int out_size)
{
    const float* vertices = (const float*)d_in[0];
    const void*  faces    = d_in[1];
    const float* uv       = (const float*)d_in[2];
    const void*  uvfaces  = d_in[3];
    const float* uvmap    = (const float*)d_in[4];
    float* out = (float*)d_out;

    dim3 blk(16, 16, 4), grd(IMG / 16, IMG / 16);
    render_kernel<<<grd, blk>>>(vertices, faces, uv, uvfaces, uvmap, out);
}